// round 1
// baseline (speedup 1.0000x reference)
#include <cuda_runtime.h>
#include <cstddef>

// Problem constants
#define BATCH 4
#define MDIM  4096
#define NDIM  4096
#define DQ    256
#define HDIM  64

// Scratch for projected Q, K, V (fp32, 4 MB each). __device__ globals: allowed.
__device__ float g_q[(size_t)BATCH * MDIM * HDIM];
__device__ float g_k[(size_t)BATCH * NDIM * HDIM];
__device__ float g_v[(size_t)BATCH * NDIM * HDIM];

// ---------------------------------------------------------------------------
// Projection: C[rows,64] = A[rows,256] @ W[256, ldw][:, coff:coff+64]
// Block: 256 threads, 64 rows. Thread t -> row r=t>>2, col group cg=t&3 (16 cols).
// ---------------------------------------------------------------------------
__global__ __launch_bounds__(256) void proj_kernel(
    const float* __restrict__ A, const float* __restrict__ W,
    float* __restrict__ C, int ldw, int coff)
{
    __shared__ float As[64 * 64];   // 16 KB: 64 rows x 64-k chunk
    __shared__ float Ws[64 * 64];   // 16 KB: 64-k chunk x 64 cols

    const int row0 = blockIdx.x * 64;
    const int t  = threadIdx.x;
    const int r  = t >> 2;
    const int cg = t & 3;

    float acc[16];
#pragma unroll
    for (int j = 0; j < 16; j++) acc[j] = 0.f;

    for (int k0 = 0; k0 < DQ; k0 += 64) {
        __syncthreads();
        // Load A tile: rows row0..row0+63, k k0..k0+63 (1024 float4, 4/thread)
#pragma unroll
        for (int i = t; i < 1024; i += 256) {
            int rr = i >> 4, kk = i & 15;
            ((float4*)As)[i] =
                *(const float4*)(A + (size_t)(row0 + rr) * DQ + k0 + kk * 4);
        }
        // Load W tile: k rows k0..k0+63, cols coff..coff+63
#pragma unroll
        for (int i = t; i < 1024; i += 256) {
            int kr = i >> 4, cc = i & 15;
            ((float4*)Ws)[i] =
                *(const float4*)(W + (size_t)(k0 + kr) * ldw + coff + cc * 4);
        }
        __syncthreads();

#pragma unroll 8
        for (int kk = 0; kk < 64; kk++) {
            float a = As[r * 64 + kk];
            const float4* wr = (const float4*)(Ws + kk * 64 + cg * 16);
#pragma unroll
            for (int j4 = 0; j4 < 4; j4++) {
                float4 w4 = wr[j4];
                acc[j4 * 4 + 0] += a * w4.x;
                acc[j4 * 4 + 1] += a * w4.y;
                acc[j4 * 4 + 2] += a * w4.z;
                acc[j4 * 4 + 3] += a * w4.w;
            }
        }
    }

    float4* Co = (float4*)(C + (size_t)(row0 + r) * 64 + cg * 16);
#pragma unroll
    for (int j4 = 0; j4 < 4; j4++)
        Co[j4] = make_float4(acc[j4 * 4 + 0], acc[j4 * 4 + 1],
                             acc[j4 * 4 + 2], acc[j4 * 4 + 3]);
}

// ---------------------------------------------------------------------------
// Flash attention: per block, 64 m-rows of one batch. Online softmax over N
// in tiles of 64. 256 threads: thread t -> row r=t>>2, lane group cg=t&3.
// The 4 lanes of a row split the 64-dim head: cg owns h/k slice [cg*16, +16).
// QK^T: per-lane 16-wide partial dot + shfl_xor(1,2) butterfly -> full s in
// all 4 lanes. PV: lane accumulates its 16-wide h slice.
// Static smem = 48 KB exactly (Ks 16K + Vs 16K + Ss 16K).
// ---------------------------------------------------------------------------
__global__ __launch_bounds__(256) void flash_kernel(
    const float* __restrict__ Q, const float* __restrict__ K,
    const float* __restrict__ V, float* __restrict__ O)
{
    __shared__ float Ks[64 * 64];
    __shared__ float Vs[64 * 64];
    __shared__ float Ss[64 * 64];

    const int b  = blockIdx.y;
    const int m0 = blockIdx.x * 64;
    const float* Qb = Q + ((size_t)b * MDIM + m0) * HDIM;
    const float* Kb = K + (size_t)b * NDIM * HDIM;
    const float* Vb = V + (size_t)b * NDIM * HDIM;

    const int t  = threadIdx.x;
    const int r  = t >> 2;
    const int cg = t & 3;

    // Load this thread's q fragment directly from global (one-time).
    float qf[16];
    {
        const float4* qp = (const float4*)(Qb + (size_t)r * HDIM + cg * 16);
#pragma unroll
        for (int j4 = 0; j4 < 4; j4++) {
            float4 v4 = qp[j4];
            qf[j4 * 4 + 0] = v4.x; qf[j4 * 4 + 1] = v4.y;
            qf[j4 * 4 + 2] = v4.z; qf[j4 * 4 + 3] = v4.w;
        }
    }

    float o[16];
#pragma unroll
    for (int j = 0; j < 16; j++) o[j] = 0.f;
    float mi = -1e30f, li = 0.f;
    const float scale = 0.125f;  // 1/sqrt(64)

    for (int nt = 0; nt < NDIM / 64; nt++) {
        __syncthreads();  // previous tile's smem reads complete
        // Stage K and V tiles (each 64x64 fp32 = 1024 float4; 4/thread each)
        const float4* K4 = (const float4*)(Kb + (size_t)nt * 64 * HDIM);
        const float4* V4 = (const float4*)(Vb + (size_t)nt * 64 * HDIM);
#pragma unroll
        for (int i = t; i < 1024; i += 256) {
            ((float4*)Ks)[i] = K4[i];
            ((float4*)Vs)[i] = V4[i];
        }
        __syncthreads();

        // --- QK^T for this row against 64 keys ---
        float tmax = -1e30f;
#pragma unroll 4
        for (int n = 0; n < 64; n++) {
            const float4* kr = (const float4*)(Ks + n * 64 + cg * 16);
            float s = 0.f;
#pragma unroll
            for (int j4 = 0; j4 < 4; j4++) {
                float4 k4 = kr[j4];
                s += qf[j4 * 4 + 0] * k4.x + qf[j4 * 4 + 1] * k4.y +
                     qf[j4 * 4 + 2] * k4.z + qf[j4 * 4 + 3] * k4.w;
            }
            s += __shfl_xor_sync(0xffffffffu, s, 1);
            s += __shfl_xor_sync(0xffffffffu, s, 2);
            s *= scale;
            Ss[r * 64 + n] = s;  // all 4 lanes write identical value
            tmax = fmaxf(tmax, s);
        }
        __syncwarp();

        // --- online softmax rescale ---
        float newm = fmaxf(mi, tmax);
        float corr = __expf(mi - newm);
        mi = newm;
        li *= corr;
#pragma unroll
        for (int j = 0; j < 16; j++) o[j] *= corr;

        // --- exp + PV accumulate ---
#pragma unroll 4
        for (int n = 0; n < 64; n++) {
            float p = __expf(Ss[r * 64 + n] - mi);
            li += p;
            const float4* vr = (const float4*)(Vs + n * 64 + cg * 16);
#pragma unroll
            for (int j4 = 0; j4 < 4; j4++) {
                float4 v4 = vr[j4];
                o[j4 * 4 + 0] += p * v4.x;
                o[j4 * 4 + 1] += p * v4.y;
                o[j4 * 4 + 2] += p * v4.z;
                o[j4 * 4 + 3] += p * v4.w;
            }
        }
    }

    const float inv = 1.f / li;
    float4* Op = (float4*)(O + ((size_t)b * MDIM + m0 + r) * HDIM + cg * 16);
#pragma unroll
    for (int j4 = 0; j4 < 4; j4++)
        Op[j4] = make_float4(o[j4 * 4 + 0] * inv, o[j4 * 4 + 1] * inv,
                             o[j4 * 4 + 2] * inv, o[j4 * 4 + 3] * inv);
}

// ---------------------------------------------------------------------------
// Launch
// ---------------------------------------------------------------------------
extern "C" void kernel_launch(void* const* d_in, const int* in_sizes, int n_in,
                              void* d_out, int out_size)
{
    const float* x    = (const float*)d_in[0];  // [B, M, DQ]
    const float* cond = (const float*)d_in[1];  // [B, N, DQ]
    const float* Wq   = (const float*)d_in[2];  // [DQ, H]
    const float* Wkv  = (const float*)d_in[3];  // [DQ, 2H]
    float* out = (float*)d_out;                 // [B, M, H]

    float *qp = nullptr, *kp = nullptr, *vp = nullptr;
    cudaGetSymbolAddress((void**)&qp, g_q);
    cudaGetSymbolAddress((void**)&kp, g_k);
    cudaGetSymbolAddress((void**)&vp, g_v);

    const int rows_q  = BATCH * MDIM;  // 16384
    const int rows_kv = BATCH * NDIM;  // 16384

    // q = x @ Wq            (ldw=64,  coff=0)
    proj_kernel<<<rows_q / 64, 256>>>(x, Wq, qp, HDIM, 0);
    // k = cond @ Wkv[:, :64] (ldw=128, coff=0)
    proj_kernel<<<rows_kv / 64, 256>>>(cond, Wkv, kp, 2 * HDIM, 0);
    // v = cond @ Wkv[:, 64:] (ldw=128, coff=64)
    proj_kernel<<<rows_kv / 64, 256>>>(cond, Wkv, vp, 2 * HDIM, HDIM);

    dim3 grid(MDIM / 64, BATCH);
    flash_kernel<<<grid, 256>>>(qp, kp, vp, out);
}

// round 3
// speedup vs baseline: 10.4280x; 10.4280x over previous
#include <cuda_runtime.h>
#include <cuda_bf16.h>
#include <cstdint>
#include <cstddef>

#define BATCH 4
#define MDIM  4096
#define NDIM  4096
#define DQK   256

static constexpr float LOG2E = 1.4426950408889634f;

// ---------------------------------------------------------------------------
// helpers
// ---------------------------------------------------------------------------
__device__ __forceinline__ uint32_t smem_u32(const void* p) {
    uint32_t a;
    asm("{ .reg .u64 t; cvta.to.shared.u64 t, %1; cvt.u32.u64 %0, t; }"
        : "=r"(a) : "l"(p));
    return a;
}

__device__ __forceinline__ float ex2f(float x) {
    float r; asm("ex2.approx.ftz.f32 %0, %1;" : "=f"(r) : "f"(x)); return r;
}

// fp32 pair -> packed bf16 hi + packed bf16 residual(lo)
__device__ __forceinline__ void split_pair(float a, float b, uint32_t& hi, uint32_t& lo) {
    __nv_bfloat162 h = __floats2bfloat162_rn(a, b);
    float r0 = a - __bfloat162float(__low2bfloat16(h));
    float r1 = b - __bfloat162float(__high2bfloat16(h));
    __nv_bfloat162 l = __floats2bfloat162_rn(r0, r1);
    hi = *reinterpret_cast<uint32_t*>(&h);
    lo = *reinterpret_cast<uint32_t*>(&l);
}

#define LDSM_X4(r0, r1, r2, r3, a) \
    asm volatile("ldmatrix.sync.aligned.m8n8.x4.shared.b16 {%0,%1,%2,%3}, [%4];" \
                 : "=r"(r0), "=r"(r1), "=r"(r2), "=r"(r3) : "r"(a))

#define LDSM_X4T(r0, r1, r2, r3, a) \
    asm volatile("ldmatrix.sync.aligned.m8n8.x4.trans.shared.b16 {%0,%1,%2,%3}, [%4];" \
                 : "=r"(r0), "=r"(r1), "=r"(r2), "=r"(r3) : "r"(a))

#define MMA16816(d, a0, a1, a2, a3, b0, b1)                                    \
    asm volatile("mma.sync.aligned.m16n8k16.row.col.f32.bf16.bf16.f32 "        \
                 "{%0,%1,%2,%3}, {%4,%5,%6,%7}, {%8,%9}, {%0,%1,%2,%3};"       \
                 : "+f"((d)[0]), "+f"((d)[1]), "+f"((d)[2]), "+f"((d)[3])      \
                 : "r"(a0), "r"(a1), "r"(a2), "r"(a3), "r"(b0), "r"(b1))

// ---------------------------------------------------------------------------
// scratch: bf16 hi/lo splits of Q(scaled), K, V — all row-major [b*4096+row][64]
// ---------------------------------------------------------------------------
__device__ __nv_bfloat16 g_qh[(size_t)BATCH * MDIM * 64];
__device__ __nv_bfloat16 g_ql[(size_t)BATCH * MDIM * 64];
__device__ __nv_bfloat16 g_kh[(size_t)BATCH * NDIM * 64];
__device__ __nv_bfloat16 g_kl[(size_t)BATCH * NDIM * 64];
__device__ __nv_bfloat16 g_vh[(size_t)BATCH * NDIM * 64];
__device__ __nv_bfloat16 g_vl[(size_t)BATCH * NDIM * 64];

// ---------------------------------------------------------------------------
// Projection: 128 rows/block, 256 threads, register-blocked SIMT GEMM.
// MODE 0 (NC=64):  q = x@Wq scaled by 0.125, split -> (o0h, o0l)
// MODE 1 (NC=128): kv = cond@Wkv; cols 0..63 -> K (o0h,o0l), 64..127 -> V (o1h,o1l)
// ---------------------------------------------------------------------------
template <int NC, int MODE>
__global__ __launch_bounds__(256) void proj_kernel(
    const float* __restrict__ A, const float* __restrict__ W,
    __nv_bfloat16* __restrict__ o0h, __nv_bfloat16* __restrict__ o0l,
    __nv_bfloat16* __restrict__ o1h, __nv_bfloat16* __restrict__ o1l)
{
    constexpr int CG    = NC / 16;
    constexpr int SLOTS = 256 / CG;
    constexpr int RPT   = 128 / SLOTS;

    __shared__ float As[128 * 36];
    __shared__ float Ws[32 * NC];

    const int t  = threadIdx.x;
    const int cg = t % CG;
    const int rs = t / CG;
    const int r0 = blockIdx.x * 128;

    float acc[RPT][16];
#pragma unroll
    for (int p = 0; p < RPT; p++)
#pragma unroll
        for (int j = 0; j < 16; j++) acc[p][j] = 0.f;

    for (int k0 = 0; k0 < DQK; k0 += 32) {
        __syncthreads();
#pragma unroll
        for (int i = t; i < 1024; i += 256) {
            int rr = i >> 3, cc = i & 7;
            *(float4*)(&As[rr * 36 + cc * 4]) =
                *(const float4*)(A + (size_t)(r0 + rr) * DQK + k0 + cc * 4);
        }
#pragma unroll
        for (int i = t; i < 32 * NC / 4; i += 256) {
            int kr = i / (NC / 4), cc = i % (NC / 4);
            *(float4*)(&Ws[kr * NC + cc * 4]) =
                *(const float4*)(W + (size_t)(k0 + kr) * NC + cc * 4);
        }
        __syncthreads();

#pragma unroll 8
        for (int kk = 0; kk < 32; kk++) {
            const float4 w0 = *(const float4*)(&Ws[kk * NC + cg * 16 + 0]);
            const float4 w1 = *(const float4*)(&Ws[kk * NC + cg * 16 + 4]);
            const float4 w2 = *(const float4*)(&Ws[kk * NC + cg * 16 + 8]);
            const float4 w3 = *(const float4*)(&Ws[kk * NC + cg * 16 + 12]);
#pragma unroll
            for (int p = 0; p < RPT; p++) {
                float a = As[(rs + p * SLOTS) * 36 + kk];
                acc[p][0]  += a * w0.x; acc[p][1]  += a * w0.y;
                acc[p][2]  += a * w0.z; acc[p][3]  += a * w0.w;
                acc[p][4]  += a * w1.x; acc[p][5]  += a * w1.y;
                acc[p][6]  += a * w1.z; acc[p][7]  += a * w1.w;
                acc[p][8]  += a * w2.x; acc[p][9]  += a * w2.y;
                acc[p][10] += a * w2.z; acc[p][11] += a * w2.w;
                acc[p][12] += a * w3.x; acc[p][13] += a * w3.y;
                acc[p][14] += a * w3.z; acc[p][15] += a * w3.w;
            }
        }
    }

#pragma unroll
    for (int p = 0; p < RPT; p++) {
        int row = r0 + rs + p * SLOTS;
        float v[16];
#pragma unroll
        for (int j = 0; j < 16; j++)
            v[j] = (MODE == 0) ? acc[p][j] * 0.125f : acc[p][j];

        uint32_t hi[8], lo[8];
#pragma unroll
        for (int j = 0; j < 8; j++) split_pair(v[2 * j], v[2 * j + 1], hi[j], lo[j]);

        __nv_bfloat16 *dh, *dl;
        int coff;
        if (MODE == 0)       { dh = o0h; dl = o0l; coff = cg * 16; }
        else if (cg < 4)     { dh = o0h; dl = o0l; coff = cg * 16; }
        else                 { dh = o1h; dl = o1l; coff = (cg - 4) * 16; }

        uint4* oh = (uint4*)(dh + (size_t)row * 64 + coff);
        uint4* ol = (uint4*)(dl + (size_t)row * 64 + coff);
        oh[0] = make_uint4(hi[0], hi[1], hi[2], hi[3]);
        oh[1] = make_uint4(hi[4], hi[5], hi[6], hi[7]);
        ol[0] = make_uint4(lo[0], lo[1], lo[2], lo[3]);
        ol[1] = make_uint4(lo[4], lo[5], lo[6], lo[7]);
    }
}

// ---------------------------------------------------------------------------
// Attention: 1 CTA = 128 q-rows of one batch, 8 warps (16 rows each).
// smem (64 KB dyn): Kh @0, Kl @16K, Vh @32K, Vl @48K. SW128 swizzle:
//   off(row, bytecol) = row*128 + (bytecol ^ ((row&7)<<4))
// ---------------------------------------------------------------------------
__global__ void __launch_bounds__(256, 1) attn_kernel(
    const __nv_bfloat16* __restrict__ Qh, const __nv_bfloat16* __restrict__ Ql,
    const __nv_bfloat16* __restrict__ Kh, const __nv_bfloat16* __restrict__ Kl,
    const __nv_bfloat16* __restrict__ Vh, const __nv_bfloat16* __restrict__ Vl,
    float* __restrict__ O)
{
    extern __shared__ char smem[];
    const uint32_t sb = smem_u32(smem);

    const int t    = threadIdx.x;
    const int w    = t >> 5, lane = t & 31;
    const int g    = lane >> 2, q4 = lane & 3;
    const int mat  = lane >> 3, r = lane & 7;
    const int bb   = blockIdx.y;
    const int m0   = blockIdx.x * 128;

    // ---- stage Q hi/lo (scaled) into smem, load A-fragments, free smem ----
    {
        const uint4* qh4 = (const uint4*)(Qh + ((size_t)(bb * MDIM + m0)) * 64);
        const uint4* ql4 = (const uint4*)(Ql + ((size_t)(bb * MDIM + m0)) * 64);
#pragma unroll
        for (int i = t; i < 1024; i += 256) {
            int row = i >> 3, c = i & 7;
            uint32_t off = (uint32_t)(row * 128) + (uint32_t)((c * 16) ^ ((row & 7) << 4));
            *(uint4*)(smem + off)         = qh4[i];
            *(uint4*)(smem + 16384 + off) = ql4[i];
        }
    }
    __syncthreads();

    uint32_t qh[4][4], ql[4][4];
#pragma unroll
    for (int kf = 0; kf < 4; kf++) {
        uint32_t off = (uint32_t)((w * 16 + (mat & 1) * 8 + r) * 128)
                     + (uint32_t)((kf * 32 + (mat >> 1) * 16) ^ (r << 4));
        LDSM_X4(qh[kf][0], qh[kf][1], qh[kf][2], qh[kf][3], sb + off);
        LDSM_X4(ql[kf][0], ql[kf][1], ql[kf][2], ql[kf][3], sb + 16384 + off);
    }
    __syncthreads();

    float oacc[8][4];
#pragma unroll
    for (int n = 0; n < 8; n++)
#pragma unroll
        for (int j = 0; j < 4; j++) oacc[n][j] = 0.f;
    float l0 = 0.f, l1 = 0.f;

    const __nv_bfloat16* KhB = Kh + (size_t)(bb * NDIM) * 64;
    const __nv_bfloat16* KlB = Kl + (size_t)(bb * NDIM) * 64;
    const __nv_bfloat16* VhB = Vh + (size_t)(bb * NDIM) * 64;
    const __nv_bfloat16* VlB = Vl + (size_t)(bb * NDIM) * 64;

    for (int nt = 0; nt < NDIM / 128; ++nt) {
        if (nt) __syncthreads();
        // ---- stage K/V hi/lo tiles [128 keys x 64] ----
        {
            const uint4* kh4 = (const uint4*)(KhB + (size_t)nt * 128 * 64);
            const uint4* kl4 = (const uint4*)(KlB + (size_t)nt * 128 * 64);
            const uint4* vh4 = (const uint4*)(VhB + (size_t)nt * 128 * 64);
            const uint4* vl4 = (const uint4*)(VlB + (size_t)nt * 128 * 64);
#pragma unroll
            for (int i = t; i < 1024; i += 256) {
                int row = i >> 3, c = i & 7;
                uint32_t off = (uint32_t)(row * 128) + (uint32_t)((c * 16) ^ ((row & 7) << 4));
                *(uint4*)(smem + off)         = kh4[i];
                *(uint4*)(smem + 16384 + off) = kl4[i];
                *(uint4*)(smem + 32768 + off) = vh4[i];
                *(uint4*)(smem + 49152 + off) = vl4[i];
            }
        }
        __syncthreads();

        // ---- S = Qh*Kh + Ql*Kh + Qh*Kl  (per warp: 16 x 128, fp32 acc) ----
        float s[16][4];
#pragma unroll
        for (int n = 0; n < 16; n++)
#pragma unroll
            for (int j = 0; j < 4; j++) s[n][j] = 0.f;

#pragma unroll
        for (int kf = 0; kf < 4; kf++) {
            uint32_t cx = (uint32_t)((kf * 32 + (mat & 1) * 16) ^ (r << 4));
#pragma unroll
            for (int tp = 0; tp < 8; tp++) {
                uint32_t a = sb + (uint32_t)((tp * 16 + (mat >> 1) * 8 + r) * 128) + cx;
                uint32_t b0, b1, b2, b3;
                LDSM_X4(b0, b1, b2, b3, a);                     // Kh frag
                MMA16816(s[2 * tp],     qh[kf][0], qh[kf][1], qh[kf][2], qh[kf][3], b0, b1);
                MMA16816(s[2 * tp + 1], qh[kf][0], qh[kf][1], qh[kf][2], qh[kf][3], b2, b3);
                MMA16816(s[2 * tp],     ql[kf][0], ql[kf][1], ql[kf][2], ql[kf][3], b0, b1);
                MMA16816(s[2 * tp + 1], ql[kf][0], ql[kf][1], ql[kf][2], ql[kf][3], b2, b3);
                LDSM_X4(b0, b1, b2, b3, a + 16384);             // Kl frag
                MMA16816(s[2 * tp],     qh[kf][0], qh[kf][1], qh[kf][2], qh[kf][3], b0, b1);
                MMA16816(s[2 * tp + 1], qh[kf][0], qh[kf][1], qh[kf][2], qh[kf][3], b2, b3);
            }
        }

        // ---- p = exp2(s*log2e); row sums; pack to bf16 hi/lo A-frags ----
        uint32_t ph[32], pl[32];
#pragma unroll
        for (int n = 0; n < 16; n++) {
            float p0 = ex2f(s[n][0] * LOG2E), p1 = ex2f(s[n][1] * LOG2E);
            float p2 = ex2f(s[n][2] * LOG2E), p3 = ex2f(s[n][3] * LOG2E);
            l0 += p0 + p1;
            l1 += p2 + p3;
            split_pair(p0, p1, ph[2 * n],     pl[2 * n]);
            split_pair(p2, p3, ph[2 * n + 1], pl[2 * n + 1]);
        }

        // ---- O += Ph*Vh + Pl*Vh + Ph*Vl  (16 x 64) ----
#pragma unroll
        for (int j = 0; j < 8; j++) {
            const uint32_t* Ah = &ph[4 * j];
            const uint32_t* Al = &pl[4 * j];
            uint32_t rowa = (uint32_t)((j * 16 + (mat & 1) * 8 + r) * 128);
#pragma unroll
            for (int hp = 0; hp < 4; hp++) {
                uint32_t a = sb + 32768 + rowa
                           + (uint32_t)((hp * 32 + (mat >> 1) * 16) ^ (r << 4));
                uint32_t b0, b1, b2, b3;
                LDSM_X4T(b0, b1, b2, b3, a);                    // Vh frag
                MMA16816(oacc[2 * hp],     Ah[0], Ah[1], Ah[2], Ah[3], b0, b1);
                MMA16816(oacc[2 * hp + 1], Ah[0], Ah[1], Ah[2], Ah[3], b2, b3);
                MMA16816(oacc[2 * hp],     Al[0], Al[1], Al[2], Al[3], b0, b1);
                MMA16816(oacc[2 * hp + 1], Al[0], Al[1], Al[2], Al[3], b2, b3);
                LDSM_X4T(b0, b1, b2, b3, a + 16384);            // Vl frag
                MMA16816(oacc[2 * hp],     Ah[0], Ah[1], Ah[2], Ah[3], b0, b1);
                MMA16816(oacc[2 * hp + 1], Ah[0], Ah[1], Ah[2], Ah[3], b2, b3);
            }
        }
    }

    // ---- epilogue: quad-reduce row sums, scale, store ----
    l0 += __shfl_xor_sync(0xffffffffu, l0, 1);
    l0 += __shfl_xor_sync(0xffffffffu, l0, 2);
    l1 += __shfl_xor_sync(0xffffffffu, l1, 1);
    l1 += __shfl_xor_sync(0xffffffffu, l1, 2);
    const float i0 = 1.f / l0, i1 = 1.f / l1;

    float* Og  = O + ((size_t)(bb * MDIM + m0 + w * 16 + g)) * 64;
    float* Og8 = Og + 8 * 64;
#pragma unroll
    for (int n = 0; n < 8; n++) {
        int col = n * 8 + q4 * 2;
        *(float2*)(Og  + col) = make_float2(oacc[n][0] * i0, oacc[n][1] * i0);
        *(float2*)(Og8 + col) = make_float2(oacc[n][2] * i1, oacc[n][3] * i1);
    }
}

// ---------------------------------------------------------------------------
// Launch
// ---------------------------------------------------------------------------
extern "C" void kernel_launch(void* const* d_in, const int* in_sizes, int n_in,
                              void* d_out, int out_size)
{
    const float* x    = (const float*)d_in[0];
    const float* cond = (const float*)d_in[1];
    const float* Wq   = (const float*)d_in[2];
    const float* Wkv  = (const float*)d_in[3];
    float* out = (float*)d_out;

    __nv_bfloat16 *qh, *ql, *kh, *kl, *vh, *vl;
    cudaGetSymbolAddress((void**)&qh, g_qh);
    cudaGetSymbolAddress((void**)&ql, g_ql);
    cudaGetSymbolAddress((void**)&kh, g_kh);
    cudaGetSymbolAddress((void**)&kl, g_kl);
    cudaGetSymbolAddress((void**)&vh, g_vh);
    cudaGetSymbolAddress((void**)&vl, g_vl);

    cudaFuncSetAttribute(attn_kernel, cudaFuncAttributeMaxDynamicSharedMemorySize,
                         65536);

    proj_kernel<64, 0><<<BATCH * MDIM / 128, 256>>>(x, Wq, qh, ql, nullptr, nullptr);
    proj_kernel<128, 1><<<BATCH * NDIM / 128, 256>>>(cond, Wkv, kh, kl, vh, vl);

    dim3 grid(MDIM / 128, BATCH);
    attn_kernel<<<grid, 256, 65536>>>(qh, ql, kh, kl, vh, vl, out);
}

// round 4
// speedup vs baseline: 17.4862x; 1.6768x over previous
#include <cuda_runtime.h>
#include <cuda_bf16.h>
#include <cstdint>
#include <cstddef>

#define BATCH 4
#define MDIM  4096
#define NDIM  4096
#define DQK   256

static constexpr float LOG2E = 1.4426950408889634f;

// ---------------------------------------------------------------------------
// helpers
// ---------------------------------------------------------------------------
__device__ __forceinline__ uint32_t smem_u32(const void* p) {
    uint32_t a;
    asm("{ .reg .u64 t; cvta.to.shared.u64 t, %1; cvt.u32.u64 %0, t; }"
        : "=r"(a) : "l"(p));
    return a;
}

__device__ __forceinline__ float ex2f(float x) {
    float r; asm("ex2.approx.ftz.f32 %0, %1;" : "=f"(r) : "f"(x)); return r;
}

// fp32 pair -> packed bf16 hi + packed bf16 residual(lo)
__device__ __forceinline__ void split_pair(float a, float b, uint32_t& hi, uint32_t& lo) {
    __nv_bfloat162 h = __floats2bfloat162_rn(a, b);
    float r0 = a - __bfloat162float(__low2bfloat16(h));
    float r1 = b - __bfloat162float(__high2bfloat16(h));
    __nv_bfloat162 l = __floats2bfloat162_rn(r0, r1);
    hi = *reinterpret_cast<uint32_t*>(&h);
    lo = *reinterpret_cast<uint32_t*>(&l);
}

#define LDSM_X4(r0, r1, r2, r3, a) \
    asm volatile("ldmatrix.sync.aligned.m8n8.x4.shared.b16 {%0,%1,%2,%3}, [%4];" \
                 : "=r"(r0), "=r"(r1), "=r"(r2), "=r"(r3) : "r"(a))

#define LDSM_X4T(r0, r1, r2, r3, a) \
    asm volatile("ldmatrix.sync.aligned.m8n8.x4.trans.shared.b16 {%0,%1,%2,%3}, [%4];" \
                 : "=r"(r0), "=r"(r1), "=r"(r2), "=r"(r3) : "r"(a))

#define MMA16816(d, a0, a1, a2, a3, b0, b1)                                    \
    asm volatile("mma.sync.aligned.m16n8k16.row.col.f32.bf16.bf16.f32 "        \
                 "{%0,%1,%2,%3}, {%4,%5,%6,%7}, {%8,%9}, {%0,%1,%2,%3};"       \
                 : "+f"((d)[0]), "+f"((d)[1]), "+f"((d)[2]), "+f"((d)[3])      \
                 : "r"(a0), "r"(a1), "r"(a2), "r"(a3), "r"(b0), "r"(b1))

#define CP_ASYNC16(dst, src) \
    asm volatile("cp.async.cg.shared.global [%0], [%1], 16;" \
                 :: "r"(dst), "l"(src) : "memory")
#define CP_COMMIT() asm volatile("cp.async.commit_group;" ::: "memory")
#define CP_WAIT1()  asm volatile("cp.async.wait_group 1;" ::: "memory")

// ---------------------------------------------------------------------------
// scratch: bf16 hi/lo splits of Q(scaled), K, V — row-major [b*4096+row][64]
// ---------------------------------------------------------------------------
__device__ __nv_bfloat16 g_qh[(size_t)BATCH * MDIM * 64];
__device__ __nv_bfloat16 g_ql[(size_t)BATCH * MDIM * 64];
__device__ __nv_bfloat16 g_kh[(size_t)BATCH * NDIM * 64];
__device__ __nv_bfloat16 g_kl[(size_t)BATCH * NDIM * 64];
__device__ __nv_bfloat16 g_vh[(size_t)BATCH * NDIM * 64];
__device__ __nv_bfloat16 g_vl[(size_t)BATCH * NDIM * 64];

// ---------------------------------------------------------------------------
// HMMA projection: C[128 rows x NC] = A[rows x 256] @ W[256 x NC], hi/lo 3-MMA.
// 256 threads / 8 warps; warp w owns rows w*16..+15. K chunks of 64.
// smem: Ah@0 (16K), Al@16K, Wh@32K (NC*128), Wl after.
// MODE 0: scale 0.125, all cols -> (o0h,o0l).  MODE 1: cols<64 -> K, else -> V.
// ---------------------------------------------------------------------------
template <int NC, int MODE>
__global__ __launch_bounds__(256) void proj_mma(
    const float* __restrict__ A, const float* __restrict__ W,
    __nv_bfloat16* __restrict__ o0h, __nv_bfloat16* __restrict__ o0l,
    __nv_bfloat16* __restrict__ o1h, __nv_bfloat16* __restrict__ o1l)
{
    extern __shared__ char sm[];
    const uint32_t sb = smem_u32(sm);
    constexpr uint32_t OFF_AL = 16384;
    constexpr uint32_t OFF_WH = 32768;
    constexpr uint32_t OFF_WL = 32768 + NC * 128;

    const int t = threadIdx.x, w = t >> 5, lane = t & 31;
    const int mat = lane >> 3, r = lane & 7;
    const int g = lane >> 2, q4 = lane & 3;
    const int r0 = blockIdx.x * 128;

    float acc[NC / 8][4];
#pragma unroll
    for (int j = 0; j < NC / 8; j++)
#pragma unroll
        for (int i = 0; i < 4; i++) acc[j][i] = 0.f;

    for (int kc = 0; kc < 4; kc++) {
        if (kc) __syncthreads();
        // stage A chunk [128 x 64] fp32 -> hi/lo bf16 (swizzled 128B rows)
#pragma unroll
        for (int i = t; i < 2048; i += 256) {
            int row = i >> 4, c4 = i & 15;
            float4 v = *(const float4*)(A + (size_t)(r0 + row) * DQK + kc * 64 + c4 * 4);
            uint32_t h0, l0, h1, l1;
            split_pair(v.x, v.y, h0, l0);
            split_pair(v.z, v.w, h1, l1);
            uint32_t off = (uint32_t)(row * 128) + (uint32_t)((c4 * 8) ^ ((row & 7) << 4));
            *(uint2*)(sm + off)          = make_uint2(h0, h1);
            *(uint2*)(sm + OFF_AL + off) = make_uint2(l0, l1);
        }
        // stage W chunk [64 x NC] fp32 -> hi/lo bf16
#pragma unroll
        for (int i = t; i < 16 * NC; i += 256) {
            int kr = i / (NC / 4), c4 = i % (NC / 4);
            float4 v = *(const float4*)(W + (size_t)(kc * 64 + kr) * NC + c4 * 4);
            uint32_t h0, l0, h1, l1;
            split_pair(v.x, v.y, h0, l0);
            split_pair(v.z, v.w, h1, l1);
            uint32_t bc = (uint32_t)(c4 * 8);
            uint32_t off = (uint32_t)(kr * NC * 2) + (bc & ~127u)
                         + ((bc & 127u) ^ (uint32_t)((kr & 7) << 4));
            *(uint2*)(sm + OFF_WH + off) = make_uint2(h0, h1);
            *(uint2*)(sm + OFF_WL + off) = make_uint2(l0, l1);
        }
        __syncthreads();

        // A fragments (hi & lo) for this warp's 16 rows, k = 0..63
        uint32_t ah[4][4], al[4][4];
#pragma unroll
        for (int kf = 0; kf < 4; kf++) {
            uint32_t off = (uint32_t)((w * 16 + (mat & 1) * 8 + r) * 128)
                         + (uint32_t)((kf * 32 + (mat >> 1) * 16) ^ (r << 4));
            LDSM_X4(ah[kf][0], ah[kf][1], ah[kf][2], ah[kf][3], sb + off);
            LDSM_X4(al[kf][0], al[kf][1], al[kf][2], al[kf][3], sb + OFF_AL + off);
        }

#pragma unroll
        for (int np = 0; np < NC / 16; np++) {
#pragma unroll
            for (int kf = 0; kf < 4; kf++) {
                int krow = kf * 16 + (mat & 1) * 8 + r;
                uint32_t bc = (uint32_t)(np * 32 + (mat >> 1) * 16);
                uint32_t off = (uint32_t)(krow * NC * 2) + (bc & ~127u)
                             + ((bc & 127u) ^ (uint32_t)((krow & 7) << 4));
                uint32_t b0, b1, b2, b3;
                LDSM_X4T(b0, b1, b2, b3, sb + OFF_WH + off);
                MMA16816(acc[2 * np],     ah[kf][0], ah[kf][1], ah[kf][2], ah[kf][3], b0, b1);
                MMA16816(acc[2 * np + 1], ah[kf][0], ah[kf][1], ah[kf][2], ah[kf][3], b2, b3);
                MMA16816(acc[2 * np],     al[kf][0], al[kf][1], al[kf][2], al[kf][3], b0, b1);
                MMA16816(acc[2 * np + 1], al[kf][0], al[kf][1], al[kf][2], al[kf][3], b2, b3);
                LDSM_X4T(b0, b1, b2, b3, sb + OFF_WL + off);
                MMA16816(acc[2 * np],     ah[kf][0], ah[kf][1], ah[kf][2], ah[kf][3], b0, b1);
                MMA16816(acc[2 * np + 1], ah[kf][0], ah[kf][1], ah[kf][2], ah[kf][3], b2, b3);
            }
        }
    }

    // epilogue: scale (Q mode), split, store packed bf16x2
    const float sc = (MODE == 0) ? 0.125f : 1.f;
    const int row = r0 + w * 16 + g;
#pragma unroll
    for (int j = 0; j < NC / 8; j++) {
        uint32_t h01, l01, h23, l23;
        split_pair(acc[j][0] * sc, acc[j][1] * sc, h01, l01);
        split_pair(acc[j][2] * sc, acc[j][3] * sc, h23, l23);
        int col = j * 8 + q4 * 2;
        __nv_bfloat16 *dh, *dl;
        int cc = col;
        if (MODE == 0 || col < 64) { dh = o0h; dl = o0l; }
        else                       { dh = o1h; dl = o1l; cc = col - 64; }
        *(uint32_t*)(dh + (size_t)row * 64 + cc)       = h01;
        *(uint32_t*)(dl + (size_t)row * 64 + cc)       = l01;
        *(uint32_t*)(dh + (size_t)(row + 8) * 64 + cc) = h23;
        *(uint32_t*)(dl + (size_t)(row + 8) * 64 + cc) = l23;
    }
}

// ---------------------------------------------------------------------------
// Attention: 1 CTA = 128 q-rows of one batch, 8 warps (16 rows each).
// Double-buffered cp.async staging: buf b at b*64KB: Kh+0, Kl+16K, Vh+32K, Vl+48K.
// ---------------------------------------------------------------------------
__device__ __forceinline__ void issue_tile(
    uint32_t sb, uint32_t buf, int nt, int t,
    const uint4* kh4, const uint4* kl4, const uint4* vh4, const uint4* vl4)
{
    const uint4* kh = kh4 + nt * 1024;
    const uint4* kl = kl4 + nt * 1024;
    const uint4* vh = vh4 + nt * 1024;
    const uint4* vl = vl4 + nt * 1024;
#pragma unroll
    for (int i = t; i < 1024; i += 256) {
        int row = i >> 3, c = i & 7;
        uint32_t off = buf + (uint32_t)(row * 128)
                     + (uint32_t)((c * 16) ^ ((row & 7) << 4));
        CP_ASYNC16(sb + off,         kh + i);
        CP_ASYNC16(sb + off + 16384, kl + i);
        CP_ASYNC16(sb + off + 32768, vh + i);
        CP_ASYNC16(sb + off + 49152, vl + i);
    }
}

__global__ void __launch_bounds__(256, 1) attn_kernel(
    const __nv_bfloat16* __restrict__ Qh, const __nv_bfloat16* __restrict__ Ql,
    const __nv_bfloat16* __restrict__ Kh, const __nv_bfloat16* __restrict__ Kl,
    const __nv_bfloat16* __restrict__ Vh, const __nv_bfloat16* __restrict__ Vl,
    float* __restrict__ O)
{
    extern __shared__ char smem[];
    const uint32_t sb = smem_u32(smem);

    const int t    = threadIdx.x;
    const int w    = t >> 5, lane = t & 31;
    const int g    = lane >> 2, q4 = lane & 3;
    const int mat  = lane >> 3, r = lane & 7;
    const int bb   = blockIdx.y;
    const int m0   = blockIdx.x * 128;

    // ---- stage Q hi/lo (pre-scaled) into smem buf0, load A-frags ----
    {
        const uint4* qh4 = (const uint4*)(Qh + ((size_t)(bb * MDIM + m0)) * 64);
        const uint4* ql4 = (const uint4*)(Ql + ((size_t)(bb * MDIM + m0)) * 64);
#pragma unroll
        for (int i = t; i < 1024; i += 256) {
            int row = i >> 3, c = i & 7;
            uint32_t off = (uint32_t)(row * 128) + (uint32_t)((c * 16) ^ ((row & 7) << 4));
            *(uint4*)(smem + off)         = qh4[i];
            *(uint4*)(smem + 16384 + off) = ql4[i];
        }
    }
    __syncthreads();

    uint32_t qh[4][4], ql[4][4];
#pragma unroll
    for (int kf = 0; kf < 4; kf++) {
        uint32_t off = (uint32_t)((w * 16 + (mat & 1) * 8 + r) * 128)
                     + (uint32_t)((kf * 32 + (mat >> 1) * 16) ^ (r << 4));
        LDSM_X4(qh[kf][0], qh[kf][1], qh[kf][2], qh[kf][3], sb + off);
        LDSM_X4(ql[kf][0], ql[kf][1], ql[kf][2], ql[kf][3], sb + 16384 + off);
    }
    __syncthreads();

    float oacc[8][4];
#pragma unroll
    for (int n = 0; n < 8; n++)
#pragma unroll
        for (int j = 0; j < 4; j++) oacc[n][j] = 0.f;
    float l0 = 0.f, l1 = 0.f;

    const uint4* kh4 = (const uint4*)(Kh + (size_t)(bb * NDIM) * 64);
    const uint4* kl4 = (const uint4*)(Kl + (size_t)(bb * NDIM) * 64);
    const uint4* vh4 = (const uint4*)(Vh + (size_t)(bb * NDIM) * 64);
    const uint4* vl4 = (const uint4*)(Vl + (size_t)(bb * NDIM) * 64);

    issue_tile(sb, 0,     0, t, kh4, kl4, vh4, vl4); CP_COMMIT();
    issue_tile(sb, 65536, 1, t, kh4, kl4, vh4, vl4); CP_COMMIT();

    for (int nt = 0; nt < NDIM / 128; ++nt) {
        CP_WAIT1();
        __syncthreads();
        const uint32_t buf = (uint32_t)(nt & 1) * 65536u;

        // ---- S = Qh*Kh + Ql*Kh + Qh*Kl  (per warp: 16 x 128) ----
        float s[16][4];
#pragma unroll
        for (int n = 0; n < 16; n++)
#pragma unroll
            for (int j = 0; j < 4; j++) s[n][j] = 0.f;

#pragma unroll
        for (int kf = 0; kf < 4; kf++) {
            uint32_t cx = (uint32_t)((kf * 32 + (mat & 1) * 16) ^ (r << 4));
#pragma unroll
            for (int tp = 0; tp < 8; tp++) {
                uint32_t a = sb + buf + (uint32_t)((tp * 16 + (mat >> 1) * 8 + r) * 128) + cx;
                uint32_t b0, b1, b2, b3;
                LDSM_X4(b0, b1, b2, b3, a);                     // Kh
                MMA16816(s[2 * tp],     qh[kf][0], qh[kf][1], qh[kf][2], qh[kf][3], b0, b1);
                MMA16816(s[2 * tp + 1], qh[kf][0], qh[kf][1], qh[kf][2], qh[kf][3], b2, b3);
                MMA16816(s[2 * tp],     ql[kf][0], ql[kf][1], ql[kf][2], ql[kf][3], b0, b1);
                MMA16816(s[2 * tp + 1], ql[kf][0], ql[kf][1], ql[kf][2], ql[kf][3], b2, b3);
                LDSM_X4(b0, b1, b2, b3, a + 16384);             // Kl
                MMA16816(s[2 * tp],     qh[kf][0], qh[kf][1], qh[kf][2], qh[kf][3], b0, b1);
                MMA16816(s[2 * tp + 1], qh[kf][0], qh[kf][1], qh[kf][2], qh[kf][3], b2, b3);
            }
        }

        // ---- p = exp2(s*log2e); row sums; pack bf16 hi/lo A-frags ----
        uint32_t ph[32], pl[32];
#pragma unroll
        for (int n = 0; n < 16; n++) {
            float p0 = ex2f(s[n][0] * LOG2E), p1 = ex2f(s[n][1] * LOG2E);
            float p2 = ex2f(s[n][2] * LOG2E), p3 = ex2f(s[n][3] * LOG2E);
            l0 += p0 + p1;
            l1 += p2 + p3;
            split_pair(p0, p1, ph[2 * n],     pl[2 * n]);
            split_pair(p2, p3, ph[2 * n + 1], pl[2 * n + 1]);
        }

        // ---- O += Ph*Vh + Pl*Vh + Ph*Vl  (16 x 64) ----
#pragma unroll
        for (int j = 0; j < 8; j++) {
            const uint32_t* Ah = &ph[4 * j];
            const uint32_t* Al = &pl[4 * j];
            uint32_t rowa = (uint32_t)((j * 16 + (mat & 1) * 8 + r) * 128);
#pragma unroll
            for (int hp = 0; hp < 4; hp++) {
                uint32_t a = sb + buf + 32768 + rowa
                           + (uint32_t)((hp * 32 + (mat >> 1) * 16) ^ (r << 4));
                uint32_t b0, b1, b2, b3;
                LDSM_X4T(b0, b1, b2, b3, a);                    // Vh
                MMA16816(oacc[2 * hp],     Ah[0], Ah[1], Ah[2], Ah[3], b0, b1);
                MMA16816(oacc[2 * hp + 1], Ah[0], Ah[1], Ah[2], Ah[3], b2, b3);
                MMA16816(oacc[2 * hp],     Al[0], Al[1], Al[2], Al[3], b0, b1);
                MMA16816(oacc[2 * hp + 1], Al[0], Al[1], Al[2], Al[3], b2, b3);
                LDSM_X4T(b0, b1, b2, b3, a + 16384);            // Vl
                MMA16816(oacc[2 * hp],     Ah[0], Ah[1], Ah[2], Ah[3], b0, b1);
                MMA16816(oacc[2 * hp + 1], Ah[0], Ah[1], Ah[2], Ah[3], b2, b3);
            }
        }

        __syncthreads();
        if (nt + 2 < NDIM / 128)
            issue_tile(sb, buf, nt + 2, t, kh4, kl4, vh4, vl4);
        CP_COMMIT();
    }

    // ---- epilogue ----
    l0 += __shfl_xor_sync(0xffffffffu, l0, 1);
    l0 += __shfl_xor_sync(0xffffffffu, l0, 2);
    l1 += __shfl_xor_sync(0xffffffffu, l1, 1);
    l1 += __shfl_xor_sync(0xffffffffu, l1, 2);
    const float i0 = 1.f / l0, i1 = 1.f / l1;

    float* Og  = O + ((size_t)(bb * MDIM + m0 + w * 16 + g)) * 64;
    float* Og8 = Og + 8 * 64;
#pragma unroll
    for (int n = 0; n < 8; n++) {
        int col = n * 8 + q4 * 2;
        *(float2*)(Og  + col) = make_float2(oacc[n][0] * i0, oacc[n][1] * i0);
        *(float2*)(Og8 + col) = make_float2(oacc[n][2] * i1, oacc[n][3] * i1);
    }
}

// ---------------------------------------------------------------------------
// Launch
// ---------------------------------------------------------------------------
extern "C" void kernel_launch(void* const* d_in, const int* in_sizes, int n_in,
                              void* d_out, int out_size)
{
    const float* x    = (const float*)d_in[0];
    const float* cond = (const float*)d_in[1];
    const float* Wq   = (const float*)d_in[2];
    const float* Wkv  = (const float*)d_in[3];
    float* out = (float*)d_out;

    __nv_bfloat16 *qh, *ql, *kh, *kl, *vh, *vl;
    cudaGetSymbolAddress((void**)&qh, g_qh);
    cudaGetSymbolAddress((void**)&ql, g_ql);
    cudaGetSymbolAddress((void**)&kh, g_kh);
    cudaGetSymbolAddress((void**)&kl, g_kl);
    cudaGetSymbolAddress((void**)&vh, g_vh);
    cudaGetSymbolAddress((void**)&vl, g_vl);

    cudaFuncSetAttribute(proj_mma<64, 0>,
                         cudaFuncAttributeMaxDynamicSharedMemorySize, 49152);
    cudaFuncSetAttribute(proj_mma<128, 1>,
                         cudaFuncAttributeMaxDynamicSharedMemorySize, 65536);
    cudaFuncSetAttribute(attn_kernel,
                         cudaFuncAttributeMaxDynamicSharedMemorySize, 131072);

    proj_mma<64, 0><<<BATCH * MDIM / 128, 256, 49152>>>(x, Wq, qh, ql, nullptr, nullptr);
    proj_mma<128, 1><<<BATCH * NDIM / 128, 256, 65536>>>(cond, Wkv, kh, kl, vh, vl);

    dim3 grid(MDIM / 128, BATCH);
    attn_kernel<<<grid, 256, 131072>>>(qh, ql, kh, kl, vh, vl, out);
}

// round 5
// speedup vs baseline: 34.2678x; 1.9597x over previous
#include <cuda_runtime.h>
#include <cuda_bf16.h>
#include <cuda_fp16.h>
#include <cstdint>
#include <cstddef>

#define BATCH 4
#define MDIM  4096
#define NDIM  4096
#define DQK   256

static constexpr float LOG2E = 1.4426950408889634f;

// ---------------------------------------------------------------------------
// helpers
// ---------------------------------------------------------------------------
__device__ __forceinline__ uint32_t smem_u32(const void* p) {
    uint32_t a;
    asm("{ .reg .u64 t; cvta.to.shared.u64 t, %1; cvt.u32.u64 %0, t; }"
        : "=r"(a) : "l"(p));
    return a;
}

__device__ __forceinline__ float ex2f(float x) {
    float r; asm("ex2.approx.ftz.f32 %0, %1;" : "=f"(r) : "f"(x)); return r;
}

// fp32 pair -> packed bf16 hi + packed bf16 residual(lo)
__device__ __forceinline__ void split_pair(float a, float b, uint32_t& hi, uint32_t& lo) {
    __nv_bfloat162 h = __floats2bfloat162_rn(a, b);
    float r0 = a - __bfloat162float(__low2bfloat16(h));
    float r1 = b - __bfloat162float(__high2bfloat16(h));
    __nv_bfloat162 l = __floats2bfloat162_rn(r0, r1);
    hi = *reinterpret_cast<uint32_t*>(&h);
    lo = *reinterpret_cast<uint32_t*>(&l);
}

__device__ __forceinline__ uint32_t pack_h2(float a, float b) {
    __half2 h = __floats2half2_rn(a, b);
    return *reinterpret_cast<uint32_t*>(&h);
}

#define LDSM_X4(r0, r1, r2, r3, a) \
    asm volatile("ldmatrix.sync.aligned.m8n8.x4.shared.b16 {%0,%1,%2,%3}, [%4];" \
                 : "=r"(r0), "=r"(r1), "=r"(r2), "=r"(r3) : "r"(a))

#define LDSM_X4T(r0, r1, r2, r3, a) \
    asm volatile("ldmatrix.sync.aligned.m8n8.x4.trans.shared.b16 {%0,%1,%2,%3}, [%4];" \
                 : "=r"(r0), "=r"(r1), "=r"(r2), "=r"(r3) : "r"(a))

#define MMA_BF16(d, a0, a1, a2, a3, b0, b1)                                    \
    asm volatile("mma.sync.aligned.m16n8k16.row.col.f32.bf16.bf16.f32 "        \
                 "{%0,%1,%2,%3}, {%4,%5,%6,%7}, {%8,%9}, {%0,%1,%2,%3};"       \
                 : "+f"((d)[0]), "+f"((d)[1]), "+f"((d)[2]), "+f"((d)[3])      \
                 : "r"(a0), "r"(a1), "r"(a2), "r"(a3), "r"(b0), "r"(b1))

#define MMA_F16(d, a0, a1, a2, a3, b0, b1)                                     \
    asm volatile("mma.sync.aligned.m16n8k16.row.col.f32.f16.f16.f32 "          \
                 "{%0,%1,%2,%3}, {%4,%5,%6,%7}, {%8,%9}, {%0,%1,%2,%3};"       \
                 : "+f"((d)[0]), "+f"((d)[1]), "+f"((d)[2]), "+f"((d)[3])      \
                 : "r"(a0), "r"(a1), "r"(a2), "r"(a3), "r"(b0), "r"(b1))

#define CP_ASYNC16(dst, src) \
    asm volatile("cp.async.cg.shared.global [%0], [%1], 16;" \
                 :: "r"(dst), "l"(src) : "memory")
#define CP_COMMIT() asm volatile("cp.async.commit_group;" ::: "memory")
#define CP_WAIT2()  asm volatile("cp.async.wait_group 2;" ::: "memory")

// ---------------------------------------------------------------------------
// scratch: fp16 Q(scaled), K, V — row-major [b*4096+row][64]
// ---------------------------------------------------------------------------
__device__ __half g_q[(size_t)BATCH * MDIM * 64];
__device__ __half g_k[(size_t)BATCH * NDIM * 64];
__device__ __half g_v[(size_t)BATCH * NDIM * 64];

// ---------------------------------------------------------------------------
// HMMA projection body: C[128 x NC] = A[128 x 256] @ W[256 x NC].
// Internals: bf16 hi/lo 3-MMA (accurate); outputs fp16.
// MODE 0: scale 0.125, all cols -> o0.   MODE 1: cols<64 -> o0(K), else o1(V).
// smem layout: Ah@0 (16K), Al@16K, Wh@32K (NC*128), Wl after. Max 64KB @NC=128.
// ---------------------------------------------------------------------------
template <int NC, int MODE>
__device__ __forceinline__ void proj_body(
    char* sm, const float* __restrict__ A, const float* __restrict__ W,
    __half* __restrict__ o0, __half* __restrict__ o1, int bi)
{
    const uint32_t sb = smem_u32(sm);
    constexpr uint32_t OFF_AL = 16384;
    constexpr uint32_t OFF_WH = 32768;
    constexpr uint32_t OFF_WL = 32768 + NC * 128;

    const int t = threadIdx.x, w = t >> 5, lane = t & 31;
    const int mat = lane >> 3, r = lane & 7;
    const int g = lane >> 2, q4 = lane & 3;
    const int r0 = bi * 128;

    float acc[NC / 8][4];
#pragma unroll
    for (int j = 0; j < NC / 8; j++)
#pragma unroll
        for (int i = 0; i < 4; i++) acc[j][i] = 0.f;

    for (int kc = 0; kc < 4; kc++) {
        if (kc) __syncthreads();
#pragma unroll
        for (int i = t; i < 2048; i += 256) {
            int row = i >> 4, c4 = i & 15;
            float4 v = *(const float4*)(A + (size_t)(r0 + row) * DQK + kc * 64 + c4 * 4);
            uint32_t h0, l0, h1, l1;
            split_pair(v.x, v.y, h0, l0);
            split_pair(v.z, v.w, h1, l1);
            uint32_t off = (uint32_t)(row * 128) + (uint32_t)((c4 * 8) ^ ((row & 7) << 4));
            *(uint2*)(sm + off)          = make_uint2(h0, h1);
            *(uint2*)(sm + OFF_AL + off) = make_uint2(l0, l1);
        }
#pragma unroll
        for (int i = t; i < 16 * NC; i += 256) {
            int kr = i / (NC / 4), c4 = i % (NC / 4);
            float4 v = *(const float4*)(W + (size_t)(kc * 64 + kr) * NC + c4 * 4);
            uint32_t h0, l0, h1, l1;
            split_pair(v.x, v.y, h0, l0);
            split_pair(v.z, v.w, h1, l1);
            uint32_t bc = (uint32_t)(c4 * 8);
            uint32_t off = (uint32_t)(kr * NC * 2) + (bc & ~127u)
                         + ((bc & 127u) ^ (uint32_t)((kr & 7) << 4));
            *(uint2*)(sm + OFF_WH + off) = make_uint2(h0, h1);
            *(uint2*)(sm + OFF_WL + off) = make_uint2(l0, l1);
        }
        __syncthreads();

        uint32_t ah[4][4], al[4][4];
#pragma unroll
        for (int kf = 0; kf < 4; kf++) {
            uint32_t off = (uint32_t)((w * 16 + (mat & 1) * 8 + r) * 128)
                         + (uint32_t)((kf * 32 + (mat >> 1) * 16) ^ (r << 4));
            LDSM_X4(ah[kf][0], ah[kf][1], ah[kf][2], ah[kf][3], sb + off);
            LDSM_X4(al[kf][0], al[kf][1], al[kf][2], al[kf][3], sb + OFF_AL + off);
        }

#pragma unroll
        for (int np = 0; np < NC / 16; np++) {
#pragma unroll
            for (int kf = 0; kf < 4; kf++) {
                int krow = kf * 16 + (mat & 1) * 8 + r;
                uint32_t bc = (uint32_t)(np * 32 + (mat >> 1) * 16);
                uint32_t off = (uint32_t)(krow * NC * 2) + (bc & ~127u)
                             + ((bc & 127u) ^ (uint32_t)((krow & 7) << 4));
                uint32_t b0, b1, b2, b3;
                LDSM_X4T(b0, b1, b2, b3, sb + OFF_WH + off);
                MMA_BF16(acc[2 * np],     ah[kf][0], ah[kf][1], ah[kf][2], ah[kf][3], b0, b1);
                MMA_BF16(acc[2 * np + 1], ah[kf][0], ah[kf][1], ah[kf][2], ah[kf][3], b2, b3);
                MMA_BF16(acc[2 * np],     al[kf][0], al[kf][1], al[kf][2], al[kf][3], b0, b1);
                MMA_BF16(acc[2 * np + 1], al[kf][0], al[kf][1], al[kf][2], al[kf][3], b2, b3);
                LDSM_X4T(b0, b1, b2, b3, sb + OFF_WL + off);
                MMA_BF16(acc[2 * np],     ah[kf][0], ah[kf][1], ah[kf][2], ah[kf][3], b0, b1);
                MMA_BF16(acc[2 * np + 1], ah[kf][0], ah[kf][1], ah[kf][2], ah[kf][3], b2, b3);
            }
        }
    }

    const float sc = (MODE == 0) ? 0.125f : 1.f;
    const int row = r0 + w * 16 + g;
#pragma unroll
    for (int j = 0; j < NC / 8; j++) {
        uint32_t p01 = pack_h2(acc[j][0] * sc, acc[j][1] * sc);
        uint32_t p23 = pack_h2(acc[j][2] * sc, acc[j][3] * sc);
        int col = j * 8 + q4 * 2;
        __half* dst = o0;
        int cc = col;
        if (MODE == 1 && col >= 64) { dst = o1; cc = col - 64; }
        *(uint32_t*)(dst + (size_t)row * 64 + cc)       = p01;
        *(uint32_t*)(dst + (size_t)(row + 8) * 64 + cc) = p23;
    }
}

// One launch, both projections in parallel: blocks [0,128) Q, [128,256) KV.
__global__ __launch_bounds__(256) void proj_all(
    const float* __restrict__ x,    const float* __restrict__ Wq,
    const float* __restrict__ cond, const float* __restrict__ Wkv,
    __half* __restrict__ q, __half* __restrict__ k, __half* __restrict__ v)
{
    extern __shared__ char sm[];
    if (blockIdx.x < 128) proj_body<64, 0>(sm, x, Wq, q, nullptr, blockIdx.x);
    else                  proj_body<128, 1>(sm, cond, Wkv, k, v, blockIdx.x - 128);
}

// ---------------------------------------------------------------------------
// Attention (fp16, 1-MMA): 1 CTA = 128 q-rows of one batch, 8 warps.
// 3-stage cp.async ring: stage s at s*32KB: K @+0 (16KB), V @+16KB.
// ---------------------------------------------------------------------------
__device__ __forceinline__ void issue_tile(
    uint32_t sb, uint32_t buf, int nt, int t,
    const uint4* k4, const uint4* v4)
{
    const uint4* k = k4 + nt * 1024;
    const uint4* v = v4 + nt * 1024;
#pragma unroll
    for (int i = t; i < 1024; i += 256) {
        int row = i >> 3, c = i & 7;
        uint32_t off = buf + (uint32_t)(row * 128)
                     + (uint32_t)((c * 16) ^ ((row & 7) << 4));
        CP_ASYNC16(sb + off,         k + i);
        CP_ASYNC16(sb + off + 16384, v + i);
    }
}

__global__ void __launch_bounds__(256, 1) attn_kernel(
    const __half* __restrict__ Q, const __half* __restrict__ K,
    const __half* __restrict__ V, float* __restrict__ O)
{
    extern __shared__ char smem[];
    const uint32_t sb = smem_u32(smem);

    const int t    = threadIdx.x;
    const int w    = t >> 5, lane = t & 31;
    const int g    = lane >> 2, q4 = lane & 3;
    const int mat  = lane >> 3, r = lane & 7;
    const int bb   = blockIdx.y;
    const int m0   = blockIdx.x * 128;

    // ---- stage Q (pre-scaled fp16) into stage0 smem, load A-frags ----
    {
        const uint4* q4p = (const uint4*)(Q + ((size_t)(bb * MDIM + m0)) * 64);
#pragma unroll
        for (int i = t; i < 1024; i += 256) {
            int row = i >> 3, c = i & 7;
            uint32_t off = (uint32_t)(row * 128) + (uint32_t)((c * 16) ^ ((row & 7) << 4));
            *(uint4*)(smem + off) = q4p[i];
        }
    }
    __syncthreads();

    uint32_t qh[4][4];
#pragma unroll
    for (int kf = 0; kf < 4; kf++) {
        uint32_t off = (uint32_t)((w * 16 + (mat & 1) * 8 + r) * 128)
                     + (uint32_t)((kf * 32 + (mat >> 1) * 16) ^ (r << 4));
        LDSM_X4(qh[kf][0], qh[kf][1], qh[kf][2], qh[kf][3], sb + off);
    }
    __syncthreads();

    float oacc[8][4];
#pragma unroll
    for (int n = 0; n < 8; n++)
#pragma unroll
        for (int j = 0; j < 4; j++) oacc[n][j] = 0.f;
    float l0 = 0.f, l1 = 0.f;

    const uint4* k4 = (const uint4*)(K + (size_t)(bb * NDIM) * 64);
    const uint4* v4 = (const uint4*)(V + (size_t)(bb * NDIM) * 64);

    issue_tile(sb, 0,     0, t, k4, v4); CP_COMMIT();
    issue_tile(sb, 32768, 1, t, k4, v4); CP_COMMIT();
    issue_tile(sb, 65536, 2, t, k4, v4); CP_COMMIT();

    for (int nt = 0; nt < NDIM / 128; ++nt) {
        CP_WAIT2();
        __syncthreads();
        const uint32_t buf = (uint32_t)(nt % 3) * 32768u;

        // ---- S = Q*K^T (per warp: 16 x 128) ----
        float s[16][4];
#pragma unroll
        for (int n = 0; n < 16; n++)
#pragma unroll
            for (int j = 0; j < 4; j++) s[n][j] = 0.f;

#pragma unroll
        for (int kf = 0; kf < 4; kf++) {
            uint32_t cx = (uint32_t)((kf * 32 + (mat & 1) * 16) ^ (r << 4));
#pragma unroll
            for (int tp = 0; tp < 8; tp++) {
                uint32_t a = sb + buf + (uint32_t)((tp * 16 + (mat >> 1) * 8 + r) * 128) + cx;
                uint32_t b0, b1, b2, b3;
                LDSM_X4(b0, b1, b2, b3, a);
                MMA_F16(s[2 * tp],     qh[kf][0], qh[kf][1], qh[kf][2], qh[kf][3], b0, b1);
                MMA_F16(s[2 * tp + 1], qh[kf][0], qh[kf][1], qh[kf][2], qh[kf][3], b2, b3);
            }
        }

        // ---- p = exp2(s*log2e); row sums; pack fp16 A-frags ----
        uint32_t ph[32];
#pragma unroll
        for (int n = 0; n < 16; n++) {
            float p0 = ex2f(s[n][0] * LOG2E), p1 = ex2f(s[n][1] * LOG2E);
            float p2 = ex2f(s[n][2] * LOG2E), p3 = ex2f(s[n][3] * LOG2E);
            l0 += p0 + p1;
            l1 += p2 + p3;
            ph[2 * n]     = pack_h2(p0, p1);
            ph[2 * n + 1] = pack_h2(p2, p3);
        }

        // ---- O += P*V (16 x 64) ----
#pragma unroll
        for (int j = 0; j < 8; j++) {
            const uint32_t* Ah = &ph[4 * j];
            uint32_t rowa = (uint32_t)((j * 16 + (mat & 1) * 8 + r) * 128);
#pragma unroll
            for (int hp = 0; hp < 4; hp++) {
                uint32_t a = sb + buf + 16384 + rowa
                           + (uint32_t)((hp * 32 + (mat >> 1) * 16) ^ (r << 4));
                uint32_t b0, b1, b2, b3;
                LDSM_X4T(b0, b1, b2, b3, a);
                MMA_F16(oacc[2 * hp],     Ah[0], Ah[1], Ah[2], Ah[3], b0, b1);
                MMA_F16(oacc[2 * hp + 1], Ah[0], Ah[1], Ah[2], Ah[3], b2, b3);
            }
        }

        __syncthreads();
        if (nt + 3 < NDIM / 128)
            issue_tile(sb, buf, nt + 3, t, k4, v4);
        CP_COMMIT();
    }

    // ---- epilogue ----
    l0 += __shfl_xor_sync(0xffffffffu, l0, 1);
    l0 += __shfl_xor_sync(0xffffffffu, l0, 2);
    l1 += __shfl_xor_sync(0xffffffffu, l1, 1);
    l1 += __shfl_xor_sync(0xffffffffu, l1, 2);
    const float i0 = 1.f / l0, i1 = 1.f / l1;

    float* Og  = O + ((size_t)(bb * MDIM + m0 + w * 16 + g)) * 64;
    float* Og8 = Og + 8 * 64;
#pragma unroll
    for (int n = 0; n < 8; n++) {
        int col = n * 8 + q4 * 2;
        *(float2*)(Og  + col) = make_float2(oacc[n][0] * i0, oacc[n][1] * i0);
        *(float2*)(Og8 + col) = make_float2(oacc[n][2] * i1, oacc[n][3] * i1);
    }
}

// ---------------------------------------------------------------------------
// Launch
// ---------------------------------------------------------------------------
extern "C" void kernel_launch(void* const* d_in, const int* in_sizes, int n_in,
                              void* d_out, int out_size)
{
    const float* x    = (const float*)d_in[0];
    const float* cond = (const float*)d_in[1];
    const float* Wq   = (const float*)d_in[2];
    const float* Wkv  = (const float*)d_in[3];
    float* out = (float*)d_out;

    __half *q, *k, *v;
    cudaGetSymbolAddress((void**)&q, g_q);
    cudaGetSymbolAddress((void**)&k, g_k);
    cudaGetSymbolAddress((void**)&v, g_v);

    cudaFuncSetAttribute(proj_all,
                         cudaFuncAttributeMaxDynamicSharedMemorySize, 65536);
    cudaFuncSetAttribute(attn_kernel,
                         cudaFuncAttributeMaxDynamicSharedMemorySize, 98304);

    proj_all<<<256, 256, 65536>>>(x, Wq, cond, Wkv, q, k, v);

    dim3 grid(MDIM / 128, BATCH);
    attn_kernel<<<grid, 256, 98304>>>(q, k, v, out);
}